// round 6
// baseline (speedup 1.0000x reference)
#include <cuda_runtime.h>
#include <cuda_fp16.h>
#include <cstdint>

// ---------------------------------------------------------------------------
// Problem constants
// ---------------------------------------------------------------------------
#define NB      32
#define S       600
#define C       768
#define HD      48
#define NHEADS  16
#define NBH     (NB * NHEADS)      // 512
#define NTOK    (NB * S)           // 19200

// 1/sqrt(48) * log2(e): softmax runs in base-2, scale folded into Q at TLE time
#define CSCALE  (0.14433756729740643f * 1.4426950408889634f)

// ---------------------------------------------------------------------------
// Scratch (fp16 Q/K/V; fp32 O). g_Qh padded: attn loads Q rows 600..639 blindly.
// ---------------------------------------------------------------------------
__device__ __half g_Qh[NBH * S * HD + 2048];
__device__ __half g_Kh[NBH * S * HD];
__device__ __half g_Vh[NBH * S * HD];
__device__ float  g_O [NBH * S * HD];

#define EX2F(d, s) asm("ex2.approx.ftz.f32 %0, %1;" : "=f"(d) : "f"(s))

// m16n8k16 f16 mma with f32 accumulate (sm_80+; valid at plain sm_100 target)
__device__ __forceinline__ void mma_f16(float c[4], const uint32_t a[4],
                                        uint32_t b0, uint32_t b1) {
    asm volatile("mma.sync.aligned.m16n8k16.row.col.f32.f16.f16.f32 "
                 "{%0,%1,%2,%3}, {%4,%5,%6,%7}, {%8,%9}, {%0,%1,%2,%3};"
                 : "+f"(c[0]), "+f"(c[1]), "+f"(c[2]), "+f"(c[3])
                 : "r"(a[0]), "r"(a[1]), "r"(a[2]), "r"(a[3]),
                   "r"(b0), "r"(b1));
}

// ---------------------------------------------------------------------------
// TLE q/k/v: one warp per token, 4 tokens per 128-thread block.
//   x staged per-warp in smem (not registers: keeps regs <=128 for occ 25%).
//   Steps communicate via warp-private smem, stride 108 (conflict-free).
// ---------------------------------------------------------------------------
#define TST 108

__global__ void __launch_bounds__(128, 4) tle_qkv_kernel(
    const float* __restrict__ x,
    const float* __restrict__ wq1, const float* __restrict__ wq2,
    const float* __restrict__ wq3, const float* __restrict__ bq,
    const float* __restrict__ wk1, const float* __restrict__ wk2,
    const float* __restrict__ wk3, const float* __restrict__ bk,
    const float* __restrict__ wv1, const float* __restrict__ wv2,
    const float* __restrict__ wv3, const float* __restrict__ bv)
{
    __shared__ float wS[816];          // 3 x (w1 64 | w2 64 | w3 144)
    __shared__ float XS[4][768];
    __shared__ float T1[4][864];
    __shared__ float T2[4][864];

    const int tid  = threadIdx.x;
    const int w    = tid >> 5;
    const int lane = tid & 31;
    const int tok  = blockIdx.x * 4 + w;
    const int b    = tok / S;
    const int s    = tok - b * S;
    const int bh0  = b * NHEADS;

    {
        const float* Wsrc[9] = {wq1, wq2, wq3, wk1, wk2, wk3, wv1, wv2, wv3};
        for (int idx = tid; idx < 816; idx += 128) {
            const int p = idx / 272, r = idx - p * 272;
            float v;
            if (r < 64)       v = Wsrc[3 * p][r];
            else if (r < 128) v = Wsrc[3 * p + 1][r - 64];
            else              v = Wsrc[3 * p + 2][r - 128];
            wS[idx] = v;
        }
    }

    // stage x into per-warp smem (coalesced float4)
    float* const xsw = XS[w];
    {
        const float4* xp4 = (const float4*)(x + (size_t)tok * C);
        float4* xd = (float4*)xsw;
        #pragma unroll
        for (int m = 0; m < 6; ++m) xd[lane + 32 * m] = xp4[lane + 32 * m];
    }
    __syncthreads();

    float* const T1w = T1[w];
    float* const T2w = T2[w];

    #pragma unroll 1
    for (int p = 0; p < 3; ++p) {
        const float* w1 = wS + p * 272;
        const float* w2 = w1 + 64;
        const float* w3 = w1 + 128;
        const float* bp = (p == 0) ? bq : (p == 1) ? bk : bv;
        __half* gdst    = (p == 0) ? g_Qh : (p == 1) ? g_Kh : g_Vh;

        // step 1: t1[a][jk] = sum_i w1[a,i] x[i][jk]   (m outer: low reg count)
        #pragma unroll 1
        for (int m = 0; m < 3; ++m) {
            const int col = lane + 32 * m;
            float xm[8];
            #pragma unroll
            for (int i = 0; i < 8; ++i) xm[i] = xsw[i * 96 + col];
            #pragma unroll
            for (int a = 0; a < 8; ++a) {
                float acc = 0.f;
                #pragma unroll
                for (int i = 0; i < 8; ++i) acc += w1[a * 8 + i] * xm[i];
                T1w[a * TST + col] = acc;
            }
        }
        __syncwarp();

        // step 2: t2[a][c*12+k] = sum_j w2[c,j] t1[a][j*12+k]
        #pragma unroll 1
        for (int m = 0; m < 3; ++m) {
            const int r2 = lane + 32 * m;
            const int a2 = r2 / 12, k2 = r2 - a2 * 12;
            float tv[8];
            #pragma unroll
            for (int j = 0; j < 8; ++j) tv[j] = T1w[a2 * TST + j * 12 + k2];
            #pragma unroll
            for (int cc = 0; cc < 8; ++cc) {
                float acc = 0.f;
                #pragma unroll
                for (int j = 0; j < 8; ++j) acc += w2[cc * 8 + j] * tv[j];
                T2w[a2 * TST + cc * 12 + k2] = acc;
            }
        }
        __syncwarp();

        // step 3: + bias, convert to half, stage in (h, dpos) head layout
        __half* const stg = (__half*)T1w;
        #pragma unroll 1
        for (int m = 0; m < 2; ++m) {
            const int r3 = lane + 32 * m;
            const int a3 = r3 >> 3, c3 = r3 & 7;
            float uv[12];
            #pragma unroll
            for (int k = 0; k < 12; ++k) uv[k] = T2w[a3 * TST + c3 * 12 + k];
            const float* bb = bp + a3 * 96 + c3 * 12;
            #pragma unroll
            for (int d = 0; d < 12; ++d) {
                float acc = bb[d];
                #pragma unroll
                for (int k = 0; k < 12; ++k) acc += w3[d * 12 + k] * uv[k];
                if (p == 0) acc *= CSCALE;
                const int h    = (a3 & 1) * 8 + (c3 & 1) * 4 + (d & 3);
                const int dpos = (a3 >> 1) * 12 + (c3 >> 1) * 3 + (d >> 2);
                stg[h * 48 + dpos] = __float2half_rn(acc);
            }
        }
        __syncwarp();

        // coalesced write: 96 uint4 (= 768 halves), 3 per lane
        const uint4* srcv = (const uint4*)stg;
        #pragma unroll
        for (int m = 0; m < 3; ++m) {
            const int v = lane + 32 * m;
            const int head = v / 6, off = v - head * 6;
            uint4* dv = (uint4*)(gdst + ((size_t)(bh0 + head) * S + s) * HD);
            dv[off] = srcv[v];
        }
        __syncwarp();
    }
}

// ---------------------------------------------------------------------------
// fp16 mma.sync flash attention, P kept in registers.
//   QK^T C-fragment layout == PV A-fragment layout (FA2 trick): pack the
//   exp2'd scores as half2 pairs and feed them straight into the PV mma.
//   No P smem buffer at all. V staged transposed via 2x2 half2 blocks.
// ---------------------------------------------------------------------------
#define SKH 56     // K tile row stride (halves)
#define SVT 66     // Vt row stride (halves)

__global__ void __launch_bounds__(256) attn_kernel()
{
    __shared__ __half Ks[64 * SKH];        // 7168 B
    __shared__ __half Vt[48 * SVT];        // 6336 B  (dim-major)

    const int tid  = threadIdx.x;
    const int wid  = tid >> 5;
    const int lane = tid & 31;
    const int gid  = lane >> 2;
    const int tig  = lane & 3;
    const int hid  = blockIdx.y;
    const int q0   = blockIdx.x * 128;

    // ---- Q fragments straight from gmem (rows >= S read pad: harmless) ----
    uint32_t qa[3][4];
    {
        const __half* Q0 = g_Qh + ((size_t)hid * S + (q0 + wid * 16 + gid)) * HD;
        const __half* Q8 = Q0 + 8 * HD;
        #pragma unroll
        for (int ks = 0; ks < 3; ++ks) {
            qa[ks][0] = *(const uint32_t*)(Q0 + ks * 16 + 2 * tig);
            qa[ks][1] = *(const uint32_t*)(Q8 + ks * 16 + 2 * tig);
            qa[ks][2] = *(const uint32_t*)(Q0 + ks * 16 + 8 + 2 * tig);
            qa[ks][3] = *(const uint32_t*)(Q8 + ks * 16 + 8 + 2 * tig);
        }
    }

    float o[6][4];
    #pragma unroll
    for (int n = 0; n < 6; ++n) { o[n][0] = o[n][1] = o[n][2] = o[n][3] = 0.f; }
    float l0 = 0.f, l1 = 0.f;

    const __half* const Kg = g_Kh + (size_t)hid * S * HD;
    const __half* const Vg = g_Vh + (size_t)hid * S * HD;

    #pragma unroll 1
    for (int t = 0; t < 10; ++t) {
        const int j0 = t * 64;
        __syncthreads();
        // stage K rows: 64 rows x 24 half2, 6 per thread
        #pragma unroll
        for (int m = 0; m < 6; ++m) {
            const int u = tid + 256 * m;
            const int row = u / 24, cu = u - row * 24, gr = j0 + row;
            const uint32_t kv = (gr < S) ? *(const uint32_t*)(Kg + gr * HD + 2 * cu) : 0u;
            *(uint32_t*)&Ks[row * SKH + 2 * cu] = kv;
        }
        // stage V transposed: 2x2 half2 blocks (32 row-pairs x 24 col-pairs)
        #pragma unroll
        for (int m = 0; m < 3; ++m) {
            const int u = tid + 256 * m;
            const int r = u / 24, cc = u - r * 24;     // keys 2r,2r+1; dims 2cc,2cc+1
            const int gr = j0 + 2 * r;
            const uint32_t va = (gr     < S) ? *(const uint32_t*)(Vg + (size_t)gr * HD + 2 * cc) : 0u;
            const uint32_t vb = (gr + 1 < S) ? *(const uint32_t*)(Vg + (size_t)(gr + 1) * HD + 2 * cc) : 0u;
            const __half2 ha = *(const __half2*)&va;
            const __half2 hb = *(const __half2*)&vb;
            *(__half2*)&Vt[(2 * cc)     * SVT + 2 * r] = __halves2half2(__low2half(ha),  __low2half(hb));
            *(__half2*)&Vt[(2 * cc + 1) * SVT + 2 * r] = __halves2half2(__high2half(ha), __high2half(hb));
        }
        __syncthreads();

        // ---- S = Q K^T, exp2, row-sum; pack P as PV A-fragments (registers) ----
        uint32_t ph[8][2];
        #pragma unroll
        for (int nb = 0; nb < 8; ++nb) {
            float c[4] = {0.f, 0.f, 0.f, 0.f};
            const __half* krow = Ks + (nb * 8 + gid) * SKH;
            #pragma unroll
            for (int ks = 0; ks < 3; ++ks) {
                const uint32_t b0 = *(const uint32_t*)(krow + ks * 16 + 2 * tig);
                const uint32_t b1 = *(const uint32_t*)(krow + ks * 16 + 8 + 2 * tig);
                mma_f16(c, qa[ks], b0, b1);
            }
            const int key0 = j0 + nb * 8 + 2 * tig;
            float p0, p1, p2, p3;
            EX2F(p0, c[0]); EX2F(p1, c[1]); EX2F(p2, c[2]); EX2F(p3, c[3]);
            if (key0     >= S) { p0 = 0.f; p2 = 0.f; }
            if (key0 + 1 >= S) { p1 = 0.f; p3 = 0.f; }
            l0 += p0 + p1;
            l1 += p2 + p3;
            const __half2 h01 = __floats2half2_rn(p0, p1);
            const __half2 h23 = __floats2half2_rn(p2, p3);
            ph[nb][0] = *(const uint32_t*)&h01;    // row gid,   cols 2tig..
            ph[nb][1] = *(const uint32_t*)&h23;    // row gid+8, cols 2tig..
        }

        // ---- O += P V  (A fragments come straight from ph) ----
        #pragma unroll
        for (int ks = 0; ks < 4; ++ks) {
            uint32_t pa[4];
            pa[0] = ph[2 * ks][0];
            pa[1] = ph[2 * ks][1];
            pa[2] = ph[2 * ks + 1][0];
            pa[3] = ph[2 * ks + 1][1];
            #pragma unroll
            for (int nb = 0; nb < 6; ++nb) {
                const __half* vrow = Vt + (nb * 8 + gid) * SVT;
                const uint32_t b0 = *(const uint32_t*)(vrow + ks * 16 + 2 * tig);
                const uint32_t b1 = *(const uint32_t*)(vrow + ks * 16 + 8 + 2 * tig);
                mma_f16(o[nb], pa, b0, b1);
            }
        }
    }

    // ---- normalize + store (f32 O) ----
    l0 += __shfl_xor_sync(0xFFFFFFFFu, l0, 1);
    l0 += __shfl_xor_sync(0xFFFFFFFFu, l0, 2);
    l1 += __shfl_xor_sync(0xFFFFFFFFu, l1, 1);
    l1 += __shfl_xor_sync(0xFFFFFFFFu, l1, 2);
    const float i0 = 1.f / l0;
    const float i1 = 1.f / l1;
    const int r0 = q0 + wid * 16 + gid;
    const int r1 = r0 + 8;
    float* const Og = g_O + (size_t)hid * S * HD;
    #pragma unroll
    for (int nb = 0; nb < 6; ++nb) {
        if (r0 < S)
            *(float2*)(Og + r0 * HD + nb * 8 + 2 * tig) = make_float2(o[nb][0] * i0, o[nb][1] * i0);
        if (r1 < S)
            *(float2*)(Og + r1 * HD + nb * 8 + 2 * tig) = make_float2(o[nb][2] * i1, o[nb][3] * i1);
    }
}

// ---------------------------------------------------------------------------
// Output TLE: warp per token. Gather = dense float4 runs within head segments
// scattered into smem; contraction pipeline reads smem directly (low regs).
// ---------------------------------------------------------------------------
__global__ void __launch_bounds__(128, 4) tle_o_kernel(
    const float* __restrict__ wo1, const float* __restrict__ wo2,
    const float* __restrict__ wo3, const float* __restrict__ bo,
    float* __restrict__ out)
{
    __shared__ float wS[272];
    __shared__ float T1[4][864];
    __shared__ float T2[4][864];

    const int tid  = threadIdx.x;
    const int w    = tid >> 5;
    const int lane = tid & 31;
    const int tok  = blockIdx.x * 4 + w;
    const int b    = tok / S;
    const int s    = tok - b * S;
    const int bh0  = b * NHEADS;

    for (int idx = tid; idx < 272; idx += 128) {
        wS[idx] = (idx < 64) ? wo1[idx] : (idx < 128) ? wo2[idx - 64] : wo3[idx - 128];
    }

    // gather merge_heads: 192 float4 segment reads -> channel-order smem
    float* const xsw = T2[w];
    #pragma unroll
    for (int m = 0; m < 6; ++m) {
        const int v = lane + 32 * m;            // 0..191
        const int head = v / 12, off = v - head * 12;
        const float4 f = ((const float4*)(g_O + ((size_t)(bh0 + head) * S + s) * HD))[off];
        const int h1 = head >> 3, h2 = (head >> 2) & 1, h3 = head & 3;
        const int dp0 = off * 4;
        #pragma unroll
        for (int jj = 0; jj < 4; ++jj) {
            const int dpos = dp0 + jj;
            const int x1 = dpos / 12, rr = dpos - x1 * 12;
            const int y1 = rr / 3,   z1 = rr - y1 * 3;
            const int chan = (2 * x1 + h1) * 96 + (2 * y1 + h2) * 12 + (4 * z1 + h3);
            xsw[chan] = (jj == 0) ? f.x : (jj == 1) ? f.y : (jj == 2) ? f.z : f.w;
        }
    }
    __syncthreads();   // weights ready (block) + xs ready (warp)

    const float* w1 = wS;
    const float* w2 = wS + 64;
    const float* w3 = wS + 128;
    float* const T1w = T1[w];
    float* const T2w = T2[w];

    // step 1 reads xsw (= T2w) and writes T1w; step 2 then overwrites T2w
    #pragma unroll 1
    for (int m = 0; m < 3; ++m) {
        const int col = lane + 32 * m;
        float xm[8];
        #pragma unroll
        for (int i = 0; i < 8; ++i) xm[i] = xsw[i * 96 + col];
        #pragma unroll
        for (int a = 0; a < 8; ++a) {
            float acc = 0.f;
            #pragma unroll
            for (int i = 0; i < 8; ++i) acc += w1[a * 8 + i] * xm[i];
            T1w[a * TST + col] = acc;
        }
    }
    __syncwarp();

    #pragma unroll 1
    for (int m = 0; m < 3; ++m) {
        const int r2 = lane + 32 * m;
        const int a2 = r2 / 12, k2 = r2 - a2 * 12;
        float tv[8];
        #pragma unroll
        for (int j = 0; j < 8; ++j) tv[j] = T1w[a2 * TST + j * 12 + k2];
        #pragma unroll
        for (int cc = 0; cc < 8; ++cc) {
            float acc = 0.f;
            #pragma unroll
            for (int j = 0; j < 8; ++j) acc += w2[cc * 8 + j] * tv[j];
            T2w[a2 * TST + cc * 12 + k2] = acc;
        }
    }
    __syncwarp();

    #pragma unroll 1
    for (int m = 0; m < 2; ++m) {
        const int r3 = lane + 32 * m;
        const int a3 = r3 >> 3, c3 = r3 & 7;
        float uv[12];
        #pragma unroll
        for (int k = 0; k < 12; ++k) uv[k] = T2w[a3 * TST + c3 * 12 + k];
        const float* bb = bo + a3 * 96 + c3 * 12;
        float res[12];
        #pragma unroll
        for (int d = 0; d < 12; ++d) {
            float acc = bb[d];
            #pragma unroll
            for (int k = 0; k < 12; ++k) acc += w3[d * 12 + k] * uv[k];
            res[d] = acc;
        }
        float4* op = (float4*)(out + (size_t)tok * C + a3 * 96 + c3 * 12);
        op[0] = make_float4(res[0], res[1], res[2],  res[3]);
        op[1] = make_float4(res[4], res[5], res[6],  res[7]);
        op[2] = make_float4(res[8], res[9], res[10], res[11]);
    }
}

// ---------------------------------------------------------------------------
// Launch
// ---------------------------------------------------------------------------
extern "C" void kernel_launch(void* const* d_in, const int* in_sizes, int n_in,
                              void* d_out, int out_size)
{
    const float* x   = (const float*)d_in[0];
    const float* wq1 = (const float*)d_in[1];
    const float* wq2 = (const float*)d_in[2];
    const float* wq3 = (const float*)d_in[3];
    const float* bq  = (const float*)d_in[4];
    const float* wk1 = (const float*)d_in[5];
    const float* wk2 = (const float*)d_in[6];
    const float* wk3 = (const float*)d_in[7];
    const float* bk  = (const float*)d_in[8];
    const float* wv1 = (const float*)d_in[9];
    const float* wv2 = (const float*)d_in[10];
    const float* wv3 = (const float*)d_in[11];
    const float* bv  = (const float*)d_in[12];
    const float* wo1 = (const float*)d_in[13];
    const float* wo2 = (const float*)d_in[14];
    const float* wo3 = (const float*)d_in[15];
    const float* bo  = (const float*)d_in[16];
    float* out = (float*)d_out;

    tle_qkv_kernel<<<NTOK / 4, 128>>>(x, wq1, wq2, wq3, bq,
                                         wk1, wk2, wk3, bk,
                                         wv1, wv2, wv3, bv);

    attn_kernel<<<dim3(5, NBH), 256>>>();

    tle_o_kernel<<<NTOK / 4, 128>>>(wo1, wo2, wo3, bo, out);
}

// round 7
// speedup vs baseline: 1.2143x; 1.2143x over previous
#include <cuda_runtime.h>
#include <cuda_fp16.h>
#include <cstdint>

// ---------------------------------------------------------------------------
// Problem constants
// ---------------------------------------------------------------------------
#define NB      32
#define S       600
#define C       768
#define HD      48
#define NHEADS  16
#define NBH     (NB * NHEADS)      // 512
#define NTOK    (NB * S)           // 19200

// 1/sqrt(48) * log2(e): softmax runs in base-2, scale folded into Q at TLE time
#define CSCALE  (0.14433756729740643f * 1.4426950408889634f)

// ---------------------------------------------------------------------------
// Scratch (fp16 Q/K/V; fp32 O). g_Qh padded: attn loads Q rows 600..639 blindly.
// ---------------------------------------------------------------------------
__device__ __half g_Qh[NBH * S * HD + 2048];
__device__ __half g_Kh[NBH * S * HD];
__device__ __half g_Vh[NBH * S * HD];
__device__ float  g_O [NBH * S * HD];

#define EX2F(d, s) asm("ex2.approx.ftz.f32 %0, %1;" : "=f"(d) : "f"(s))

// m16n8k16 f16 mma with f32 accumulate (sm_80+; valid at plain sm_100 target)
__device__ __forceinline__ void mma_f16(float c[4], const uint32_t a[4],
                                        uint32_t b0, uint32_t b1) {
    asm volatile("mma.sync.aligned.m16n8k16.row.col.f32.f16.f16.f32 "
                 "{%0,%1,%2,%3}, {%4,%5,%6,%7}, {%8,%9}, {%0,%1,%2,%3};"
                 : "+f"(c[0]), "+f"(c[1]), "+f"(c[2]), "+f"(c[3])
                 : "r"(a[0]), "r"(a[1]), "r"(a[2]), "r"(a[3]),
                   "r"(b0), "r"(b1));
}

// ---------------------------------------------------------------------------
// TLE q/k/v: one warp per token, 4 tokens per 128-thread block.
//   (R5 version: x held in registers across all three projections — high ILP
//    beats high occupancy for this LSU-latency-bound kernel.)
// ---------------------------------------------------------------------------
#define TST 108

__global__ void __launch_bounds__(128) tle_qkv_kernel(
    const float* __restrict__ x,
    const float* __restrict__ wq1, const float* __restrict__ wq2,
    const float* __restrict__ wq3, const float* __restrict__ bq,
    const float* __restrict__ wk1, const float* __restrict__ wk2,
    const float* __restrict__ wk3, const float* __restrict__ bk,
    const float* __restrict__ wv1, const float* __restrict__ wv2,
    const float* __restrict__ wv3, const float* __restrict__ bv)
{
    __shared__ float wS[816];          // 3 x (w1 64 | w2 64 | w3 144)
    __shared__ float T1[4][864];
    __shared__ float T2[4][864];

    const int tid  = threadIdx.x;
    const int w    = tid >> 5;
    const int lane = tid & 31;
    const int tok  = blockIdx.x * 4 + w;
    const int b    = tok / S;
    const int s    = tok - b * S;
    const int bh0  = b * NHEADS;

    {
        const float* Wsrc[9] = {wq1, wq2, wq3, wk1, wk2, wk3, wv1, wv2, wv3};
        for (int idx = tid; idx < 816; idx += 128) {
            const int p = idx / 272, r = idx - p * 272;
            float v;
            if (r < 64)       v = Wsrc[3 * p][r];
            else if (r < 128) v = Wsrc[3 * p + 1][r - 64];
            else              v = Wsrc[3 * p + 2][r - 128];
            wS[idx] = v;
        }
    }

    // x into registers: xv[i][m] = x[i*96 + lane + 32m]  (coalesced)
    float xv[24];
    {
        const float* xp = x + (size_t)tok * C;
        #pragma unroll
        for (int m = 0; m < 3; ++m)
            #pragma unroll
            for (int i = 0; i < 8; ++i)
                xv[i * 3 + m] = xp[i * 96 + lane + 32 * m];
    }
    __syncthreads();

    float* const T1w = T1[w];
    float* const T2w = T2[w];

    #pragma unroll
    for (int p = 0; p < 3; ++p) {
        const float* w1 = wS + p * 272;
        const float* w2 = w1 + 64;
        const float* w3 = w1 + 128;
        const float* bp = (p == 0) ? bq : (p == 1) ? bk : bv;
        __half* gdst    = (p == 0) ? g_Qh : (p == 1) ? g_Kh : g_Vh;

        // step 1: t1[a][jk] = sum_i w1[a,i] x[i][jk]
        #pragma unroll
        for (int a = 0; a < 8; ++a) {
            float wr[8];
            #pragma unroll
            for (int i = 0; i < 8; ++i) wr[i] = w1[a * 8 + i];
            #pragma unroll
            for (int m = 0; m < 3; ++m) {
                float acc = 0.f;
                #pragma unroll
                for (int i = 0; i < 8; ++i) acc += wr[i] * xv[i * 3 + m];
                T1w[a * TST + lane + 32 * m] = acc;
            }
        }
        __syncwarp();

        // step 2: t2[a][c*12+k] = sum_j w2[c,j] t1[a][j*12+k]
        #pragma unroll
        for (int m = 0; m < 3; ++m) {
            const int r2 = lane + 32 * m;
            const int a2 = r2 / 12, k2 = r2 - a2 * 12;
            float tv[8];
            #pragma unroll
            for (int j = 0; j < 8; ++j) tv[j] = T1w[a2 * TST + j * 12 + k2];
            #pragma unroll
            for (int cc = 0; cc < 8; ++cc) {
                float acc = 0.f;
                #pragma unroll
                for (int j = 0; j < 8; ++j) acc += w2[cc * 8 + j] * tv[j];
                T2w[a2 * TST + cc * 12 + k2] = acc;
            }
        }
        __syncwarp();

        // step 3: + bias, convert to half, stage in (h, dpos) head layout
        __half* const stg = (__half*)T1w;
        #pragma unroll
        for (int m = 0; m < 2; ++m) {
            const int r3 = lane + 32 * m;
            const int a3 = r3 >> 3, c3 = r3 & 7;
            float uv[12];
            #pragma unroll
            for (int k = 0; k < 12; ++k) uv[k] = T2w[a3 * TST + c3 * 12 + k];
            const float* bb = bp + a3 * 96 + c3 * 12;
            #pragma unroll
            for (int d = 0; d < 12; ++d) {
                float acc = bb[d];
                #pragma unroll
                for (int k = 0; k < 12; ++k) acc += w3[d * 12 + k] * uv[k];
                if (p == 0) acc *= CSCALE;
                const int h    = (a3 & 1) * 8 + (c3 & 1) * 4 + (d & 3);
                const int dpos = (a3 >> 1) * 12 + (c3 >> 1) * 3 + (d >> 2);
                stg[h * 48 + dpos] = __float2half_rn(acc);
            }
        }
        __syncwarp();

        // coalesced write: 96 uint4 (= 768 halves), 3 per lane
        const uint4* srcv = (const uint4*)stg;
        #pragma unroll
        for (int m = 0; m < 3; ++m) {
            const int v = lane + 32 * m;
            const int head = v / 6, off = v - head * 6;
            uint4* dv = (uint4*)(gdst + ((size_t)(bh0 + head) * S + s) * HD);
            dv[off] = srcv[v];
        }
        __syncwarp();
    }
}

// ---------------------------------------------------------------------------
// fp16 mma.sync flash attention, P kept in registers (FA2 fragment trick),
// K/V staging software-pipelined: tile t+1 loaded into registers while tile t
// computes; regs committed to smem behind the barrier.
// ---------------------------------------------------------------------------
#define SKH 56     // K tile row stride (halves)
#define SVT 66     // Vt row stride (halves)

__global__ void __launch_bounds__(256) attn_kernel()
{
    __shared__ __half Ks[64 * SKH];        // 7168 B
    __shared__ __half Vt[48 * SVT];        // 6336 B  (dim-major)

    const int tid  = threadIdx.x;
    const int wid  = tid >> 5;
    const int lane = tid & 31;
    const int gid  = lane >> 2;
    const int tig  = lane & 3;
    const int hid  = blockIdx.y;
    const int q0   = blockIdx.x * 128;

    // ---- Q fragments straight from gmem (rows >= S read pad: harmless) ----
    uint32_t qa[3][4];
    {
        const __half* Q0 = g_Qh + ((size_t)hid * S + (q0 + wid * 16 + gid)) * HD;
        const __half* Q8 = Q0 + 8 * HD;
        #pragma unroll
        for (int ks = 0; ks < 3; ++ks) {
            qa[ks][0] = *(const uint32_t*)(Q0 + ks * 16 + 2 * tig);
            qa[ks][1] = *(const uint32_t*)(Q8 + ks * 16 + 2 * tig);
            qa[ks][2] = *(const uint32_t*)(Q0 + ks * 16 + 8 + 2 * tig);
            qa[ks][3] = *(const uint32_t*)(Q8 + ks * 16 + 8 + 2 * tig);
        }
    }

    float o[6][4];
    #pragma unroll
    for (int n = 0; n < 6; ++n) { o[n][0] = o[n][1] = o[n][2] = o[n][3] = 0.f; }
    float l0 = 0.f, l1 = 0.f;

    const __half* const Kg = g_Kh + (size_t)hid * S * HD;
    const __half* const Vg = g_Vh + (size_t)hid * S * HD;

    // staging roles (constant per thread)
    const int krow = tid / 24;            // K: rows tid/24 stepping by 256/24...
    const int kcu  = tid - krow * 24;     //    handled via linear u = tid + 256m
    (void)krow; (void)kcu;

    // prefetch registers
    uint32_t kreg[6], vra[3], vrb[3];

    #define LOAD_TILE(j0)                                                          \
    do {                                                                           \
        _Pragma("unroll")                                                          \
        for (int m = 0; m < 6; ++m) {                                              \
            const int u = tid + 256 * m;                                           \
            const int row = u / 24, cu = u - row * 24, gr = (j0) + row;            \
            kreg[m] = (gr < S) ? *(const uint32_t*)(Kg + (size_t)gr * HD + 2 * cu) \
                               : 0u;                                               \
        }                                                                          \
        _Pragma("unroll")                                                          \
        for (int m = 0; m < 3; ++m) {                                              \
            const int u = tid + 256 * m;                                           \
            const int r = u / 24, cc = u - r * 24;                                 \
            const int gr = (j0) + 2 * r;                                           \
            vra[m] = (gr     < S) ? *(const uint32_t*)(Vg + (size_t)gr * HD + 2 * cc) : 0u; \
            vrb[m] = (gr + 1 < S) ? *(const uint32_t*)(Vg + (size_t)(gr + 1) * HD + 2 * cc) : 0u; \
        }                                                                          \
    } while (0)

    #define STORE_TILE()                                                           \
    do {                                                                           \
        _Pragma("unroll")                                                          \
        for (int m = 0; m < 6; ++m) {                                              \
            const int u = tid + 256 * m;                                           \
            const int row = u / 24, cu = u - row * 24;                             \
            *(uint32_t*)&Ks[row * SKH + 2 * cu] = kreg[m];                         \
        }                                                                          \
        _Pragma("unroll")                                                          \
        for (int m = 0; m < 3; ++m) {                                              \
            const int u = tid + 256 * m;                                           \
            const int r = u / 24, cc = u - r * 24;                                 \
            const __half2 ha = *(const __half2*)&vra[m];                           \
            const __half2 hb = *(const __half2*)&vrb[m];                           \
            *(__half2*)&Vt[(2 * cc)     * SVT + 2 * r] =                           \
                __halves2half2(__low2half(ha),  __low2half(hb));                   \
            *(__half2*)&Vt[(2 * cc + 1) * SVT + 2 * r] =                           \
                __halves2half2(__high2half(ha), __high2half(hb));                  \
        }                                                                          \
    } while (0)

    LOAD_TILE(0);

    #pragma unroll 1
    for (int t = 0; t < 10; ++t) {
        const int j0 = t * 64;
        __syncthreads();          // previous tile's compute done; smem free
        STORE_TILE();
        __syncthreads();          // tile t staged
        if (t < 9) LOAD_TILE(j0 + 64);   // issue t+1 LDGs, hide behind MMAs

        // ---- S = Q K^T, exp2, row-sum; pack P as PV A-fragments (registers) ----
        uint32_t ph[8][2];
        #pragma unroll
        for (int nb = 0; nb < 8; ++nb) {
            float c[4] = {0.f, 0.f, 0.f, 0.f};
            const __half* krw = Ks + (nb * 8 + gid) * SKH;
            #pragma unroll
            for (int ks = 0; ks < 3; ++ks) {
                const uint32_t b0 = *(const uint32_t*)(krw + ks * 16 + 2 * tig);
                const uint32_t b1 = *(const uint32_t*)(krw + ks * 16 + 8 + 2 * tig);
                mma_f16(c, qa[ks], b0, b1);
            }
            const int key0 = j0 + nb * 8 + 2 * tig;
            float p0, p1, p2, p3;
            EX2F(p0, c[0]); EX2F(p1, c[1]); EX2F(p2, c[2]); EX2F(p3, c[3]);
            if (key0     >= S) { p0 = 0.f; p2 = 0.f; }
            if (key0 + 1 >= S) { p1 = 0.f; p3 = 0.f; }
            l0 += p0 + p1;
            l1 += p2 + p3;
            const __half2 h01 = __floats2half2_rn(p0, p1);
            const __half2 h23 = __floats2half2_rn(p2, p3);
            ph[nb][0] = *(const uint32_t*)&h01;    // row gid,   cols 2tig..
            ph[nb][1] = *(const uint32_t*)&h23;    // row gid+8, cols 2tig..
        }

        // ---- O += P V  (A fragments come straight from ph) ----
        #pragma unroll
        for (int ks = 0; ks < 4; ++ks) {
            uint32_t pa[4];
            pa[0] = ph[2 * ks][0];
            pa[1] = ph[2 * ks][1];
            pa[2] = ph[2 * ks + 1][0];
            pa[3] = ph[2 * ks + 1][1];
            #pragma unroll
            for (int nb = 0; nb < 6; ++nb) {
                const __half* vrow = Vt + (nb * 8 + gid) * SVT;
                const uint32_t b0 = *(const uint32_t*)(vrow + ks * 16 + 2 * tig);
                const uint32_t b1 = *(const uint32_t*)(vrow + ks * 16 + 8 + 2 * tig);
                mma_f16(o[nb], pa, b0, b1);
            }
        }
    }

    // ---- normalize + store (f32 O) ----
    l0 += __shfl_xor_sync(0xFFFFFFFFu, l0, 1);
    l0 += __shfl_xor_sync(0xFFFFFFFFu, l0, 2);
    l1 += __shfl_xor_sync(0xFFFFFFFFu, l1, 1);
    l1 += __shfl_xor_sync(0xFFFFFFFFu, l1, 2);
    const float i0 = 1.f / l0;
    const float i1 = 1.f / l1;
    const int r0 = q0 + wid * 16 + gid;
    const int r1 = r0 + 8;
    float* const Og = g_O + (size_t)hid * S * HD;
    #pragma unroll
    for (int nb = 0; nb < 6; ++nb) {
        if (r0 < S)
            *(float2*)(Og + r0 * HD + nb * 8 + 2 * tig) = make_float2(o[nb][0] * i0, o[nb][1] * i0);
        if (r1 < S)
            *(float2*)(Og + r1 * HD + nb * 8 + 2 * tig) = make_float2(o[nb][2] * i1, o[nb][3] * i1);
    }
}

// ---------------------------------------------------------------------------
// Output TLE (R5 version): warp per token, dense float4 gather, registers-first.
// ---------------------------------------------------------------------------
__global__ void __launch_bounds__(128) tle_o_kernel(
    const float* __restrict__ wo1, const float* __restrict__ wo2,
    const float* __restrict__ wo3, const float* __restrict__ bo,
    float* __restrict__ out)
{
    __shared__ float wS[272];
    __shared__ float T1[4][864];
    __shared__ float T2[4][864];

    const int tid  = threadIdx.x;
    const int w    = tid >> 5;
    const int lane = tid & 31;
    const int tok  = blockIdx.x * 4 + w;
    const int b    = tok / S;
    const int s    = tok - b * S;
    const int bh0  = b * NHEADS;

    for (int idx = tid; idx < 272; idx += 128) {
        wS[idx] = (idx < 64) ? wo1[idx] : (idx < 128) ? wo2[idx - 64] : wo3[idx - 128];
    }

    // gather merge_heads: 192 float4 segment reads -> channel-order smem
    float* const xsw = T2[w];
    #pragma unroll
    for (int m = 0; m < 6; ++m) {
        const int v = lane + 32 * m;            // 0..191
        const int head = v / 12, off = v - head * 12;
        const float4 f = ((const float4*)(g_O + ((size_t)(bh0 + head) * S + s) * HD))[off];
        const int h1 = head >> 3, h2 = (head >> 2) & 1, h3 = head & 3;
        const int dp0 = off * 4;
        #pragma unroll
        for (int jj = 0; jj < 4; ++jj) {
            const int dpos = dp0 + jj;
            const int x1 = dpos / 12, rr = dpos - x1 * 12;
            const int y1 = rr / 3,   z1 = rr - y1 * 3;
            const int chan = (2 * x1 + h1) * 96 + (2 * y1 + h2) * 12 + (4 * z1 + h3);
            xsw[chan] = (jj == 0) ? f.x : (jj == 1) ? f.y : (jj == 2) ? f.z : f.w;
        }
    }
    __syncthreads();   // weights ready (block) + xs ready (warp)

    const float* w1 = wS;
    const float* w2 = wS + 64;
    const float* w3 = wS + 128;
    float* const T1w = T1[w];
    float* const T2w = T2[w];

    // x into registers, then same 3-step pipeline
    float xv[24];
    #pragma unroll
    for (int m = 0; m < 3; ++m)
        #pragma unroll
        for (int i = 0; i < 8; ++i)
            xv[i * 3 + m] = xsw[i * 96 + lane + 32 * m];
    __syncwarp();

    #pragma unroll
    for (int a = 0; a < 8; ++a) {
        float wr[8];
        #pragma unroll
        for (int i = 0; i < 8; ++i) wr[i] = w1[a * 8 + i];
        #pragma unroll
        for (int m = 0; m < 3; ++m) {
            float acc = 0.f;
            #pragma unroll
            for (int i = 0; i < 8; ++i) acc += wr[i] * xv[i * 3 + m];
            T1w[a * TST + lane + 32 * m] = acc;
        }
    }
    __syncwarp();

    #pragma unroll
    for (int m = 0; m < 3; ++m) {
        const int r2 = lane + 32 * m;
        const int a2 = r2 / 12, k2 = r2 - a2 * 12;
        float tv[8];
        #pragma unroll
        for (int j = 0; j < 8; ++j) tv[j] = T1w[a2 * TST + j * 12 + k2];
        #pragma unroll
        for (int cc = 0; cc < 8; ++cc) {
            float acc = 0.f;
            #pragma unroll
            for (int j = 0; j < 8; ++j) acc += w2[cc * 8 + j] * tv[j];
            T2w[a2 * TST + cc * 12 + k2] = acc;
        }
    }
    __syncwarp();

    #pragma unroll
    for (int m = 0; m < 2; ++m) {
        const int r3 = lane + 32 * m;
        const int a3 = r3 >> 3, c3 = r3 & 7;
        float uv[12];
        #pragma unroll
        for (int k = 0; k < 12; ++k) uv[k] = T2w[a3 * TST + c3 * 12 + k];
        const float* bb = bo + a3 * 96 + c3 * 12;
        float res[12];
        #pragma unroll
        for (int d = 0; d < 12; ++d) {
            float acc = bb[d];
            #pragma unroll
            for (int k = 0; k < 12; ++k) acc += w3[d * 12 + k] * uv[k];
            res[d] = acc;
        }
        float4* op = (float4*)(out + (size_t)tok * C + a3 * 96 + c3 * 12);
        op[0] = make_float4(res[0], res[1], res[2],  res[3]);
        op[1] = make_float4(res[4], res[5], res[6],  res[7]);
        op[2] = make_float4(res[8], res[9], res[10], res[11]);
    }
}

// ---------------------------------------------------------------------------
// Launch
// ---------------------------------------------------------------------------
extern "C" void kernel_launch(void* const* d_in, const int* in_sizes, int n_in,
                              void* d_out, int out_size)
{
    const float* x   = (const float*)d_in[0];
    const float* wq1 = (const float*)d_in[1];
    const float* wq2 = (const float*)d_in[2];
    const float* wq3 = (const float*)d_in[3];
    const float* bq  = (const float*)d_in[4];
    const float* wk1 = (const float*)d_in[5];
    const float* wk2 = (const float*)d_in[6];
    const float* wk3 = (const float*)d_in[7];
    const float* bk  = (const float*)d_in[8];
    const float* wv1 = (const float*)d_in[9];
    const float* wv2 = (const float*)d_in[10];
    const float* wv3 = (const float*)d_in[11];
    const float* bv  = (const float*)d_in[12];
    const float* wo1 = (const float*)d_in[13];
    const float* wo2 = (const float*)d_in[14];
    const float* wo3 = (const float*)d_in[15];
    const float* bo  = (const float*)d_in[16];
    float* out = (float*)d_out;

    tle_qkv_kernel<<<NTOK / 4, 128>>>(x, wq1, wq2, wq3, bq,
                                         wk1, wk2, wk3, bk,
                                         wv1, wv2, wv3, bv);

    attn_kernel<<<dim3(5, NBH), 256>>>();

    tle_o_kernel<<<NTOK / 4, 128>>>(wo1, wo2, wo3, bo, out);
}

// round 8
// speedup vs baseline: 1.3196x; 1.0867x over previous
#include <cuda_runtime.h>
#include <cuda_fp16.h>
#include <cstdint>

// ---------------------------------------------------------------------------
// Problem constants
// ---------------------------------------------------------------------------
#define NB      32
#define S       600
#define C       768
#define HD      48
#define NHEADS  16
#define NBH     (NB * NHEADS)      // 512
#define NTOK    (NB * S)           // 19200

// 1/sqrt(48) * log2(e): softmax runs in base-2, scale folded into Q at TLE time
#define CSCALE  (0.14433756729740643f * 1.4426950408889634f)

// ---------------------------------------------------------------------------
// Scratch (fp16 Q/K/V/O). g_Qh padded: attn loads Q rows 600..639 blindly.
// ---------------------------------------------------------------------------
__device__ __half g_Qh[NBH * S * HD + 2048];
__device__ __half g_Kh[NBH * S * HD];
__device__ __half g_Vh[NBH * S * HD];
__device__ __half g_Oh[NBH * S * HD];

#define EX2F(d, s) asm("ex2.approx.ftz.f32 %0, %1;" : "=f"(d) : "f"(s))

__device__ __forceinline__ uint32_t smem_u32(const void* p) {
    uint32_t a;
    asm("{ .reg .u64 t; cvta.to.shared.u64 t, %1; cvt.u32.u64 %0, t; }"
        : "=r"(a) : "l"(p));
    return a;
}

// m16n8k16 f16 mma with f32 accumulate (sm_80+; valid at plain sm_100 target)
__device__ __forceinline__ void mma_f16(float c[4], const uint32_t a[4],
                                        uint32_t b0, uint32_t b1) {
    asm volatile("mma.sync.aligned.m16n8k16.row.col.f32.f16.f16.f32 "
                 "{%0,%1,%2,%3}, {%4,%5,%6,%7}, {%8,%9}, {%0,%1,%2,%3};"
                 : "+f"(c[0]), "+f"(c[1]), "+f"(c[2]), "+f"(c[3])
                 : "r"(a[0]), "r"(a[1]), "r"(a[2]), "r"(a[3]),
                   "r"(b0), "r"(b1));
}

__device__ __forceinline__ void ldsm_x4(uint32_t r[4], uint32_t addr) {
    asm volatile("ldmatrix.sync.aligned.m8n8.x4.shared.b16 {%0,%1,%2,%3}, [%4];"
                 : "=r"(r[0]), "=r"(r[1]), "=r"(r[2]), "=r"(r[3]) : "r"(addr));
}
__device__ __forceinline__ void ldsm_x2(uint32_t r[2], uint32_t addr) {
    asm volatile("ldmatrix.sync.aligned.m8n8.x2.shared.b16 {%0,%1}, [%2];"
                 : "=r"(r[0]), "=r"(r[1]) : "r"(addr));
}

// ---------------------------------------------------------------------------
// TLE q/k/v: one warp per token, 4 tokens per block. x in registers (high
// ILP); p-loop NOT unrolled (register-pressure experiment: target 3 CTAs/SM).
// ---------------------------------------------------------------------------
#define TST 108

__global__ void __launch_bounds__(128) tle_qkv_kernel(
    const float* __restrict__ x,
    const float* __restrict__ wq1, const float* __restrict__ wq2,
    const float* __restrict__ wq3, const float* __restrict__ bq,
    const float* __restrict__ wk1, const float* __restrict__ wk2,
    const float* __restrict__ wk3, const float* __restrict__ bk,
    const float* __restrict__ wv1, const float* __restrict__ wv2,
    const float* __restrict__ wv3, const float* __restrict__ bv)
{
    __shared__ float wS[816];          // 3 x (w1 64 | w2 64 | w3 144)
    __shared__ float T1[4][864];
    __shared__ float T2[4][864];

    const int tid  = threadIdx.x;
    const int w    = tid >> 5;
    const int lane = tid & 31;
    const int tok  = blockIdx.x * 4 + w;
    const int b    = tok / S;
    const int s    = tok - b * S;
    const int bh0  = b * NHEADS;

    {
        const float* Wsrc[9] = {wq1, wq2, wq3, wk1, wk2, wk3, wv1, wv2, wv3};
        for (int idx = tid; idx < 816; idx += 128) {
            const int p = idx / 272, r = idx - p * 272;
            float v;
            if (r < 64)       v = Wsrc[3 * p][r];
            else if (r < 128) v = Wsrc[3 * p + 1][r - 64];
            else              v = Wsrc[3 * p + 2][r - 128];
            wS[idx] = v;
        }
    }

    // x into registers: xv[i][m] = x[i*96 + lane + 32m]  (coalesced)
    float xv[24];
    {
        const float* xp = x + (size_t)tok * C;
        #pragma unroll
        for (int m = 0; m < 3; ++m)
            #pragma unroll
            for (int i = 0; i < 8; ++i)
                xv[i * 3 + m] = xp[i * 96 + lane + 32 * m];
    }
    __syncthreads();

    float* const T1w = T1[w];
    float* const T2w = T2[w];

    #pragma unroll 1
    for (int p = 0; p < 3; ++p) {
        const float* w1 = wS + p * 272;
        const float* w2 = w1 + 64;
        const float* w3 = w1 + 128;
        const float* bp = (p == 0) ? bq : (p == 1) ? bk : bv;
        __half* gdst    = (p == 0) ? g_Qh : (p == 1) ? g_Kh : g_Vh;

        // step 1: t1[a][jk] = sum_i w1[a,i] x[i][jk]
        #pragma unroll
        for (int a = 0; a < 8; ++a) {
            float wr[8];
            #pragma unroll
            for (int i = 0; i < 8; ++i) wr[i] = w1[a * 8 + i];
            #pragma unroll
            for (int m = 0; m < 3; ++m) {
                float acc = 0.f;
                #pragma unroll
                for (int i = 0; i < 8; ++i) acc += wr[i] * xv[i * 3 + m];
                T1w[a * TST + lane + 32 * m] = acc;
            }
        }
        __syncwarp();

        // step 2: t2[a][c*12+k] = sum_j w2[c,j] t1[a][j*12+k]
        #pragma unroll
        for (int m = 0; m < 3; ++m) {
            const int r2 = lane + 32 * m;
            const int a2 = r2 / 12, k2 = r2 - a2 * 12;
            float tv[8];
            #pragma unroll
            for (int j = 0; j < 8; ++j) tv[j] = T1w[a2 * TST + j * 12 + k2];
            #pragma unroll
            for (int cc = 0; cc < 8; ++cc) {
                float acc = 0.f;
                #pragma unroll
                for (int j = 0; j < 8; ++j) acc += w2[cc * 8 + j] * tv[j];
                T2w[a2 * TST + cc * 12 + k2] = acc;
            }
        }
        __syncwarp();

        // step 3: + bias, convert to half, stage in (h, dpos) head layout
        __half* const stg = (__half*)T1w;
        #pragma unroll
        for (int m = 0; m < 2; ++m) {
            const int r3 = lane + 32 * m;
            const int a3 = r3 >> 3, c3 = r3 & 7;
            float uv[12];
            #pragma unroll
            for (int k = 0; k < 12; ++k) uv[k] = T2w[a3 * TST + c3 * 12 + k];
            const float* bb = bp + a3 * 96 + c3 * 12;
            #pragma unroll
            for (int d = 0; d < 12; ++d) {
                float acc = bb[d];
                #pragma unroll
                for (int k = 0; k < 12; ++k) acc += w3[d * 12 + k] * uv[k];
                if (p == 0) acc *= CSCALE;
                const int h    = (a3 & 1) * 8 + (c3 & 1) * 4 + (d & 3);
                const int dpos = (a3 >> 1) * 12 + (c3 >> 1) * 3 + (d >> 2);
                stg[h * 48 + dpos] = __float2half_rn(acc);
            }
        }
        __syncwarp();

        // coalesced write: 96 uint4 (= 768 halves), 3 per lane
        const uint4* srcv = (const uint4*)stg;
        #pragma unroll
        for (int m = 0; m < 3; ++m) {
            const int v = lane + 32 * m;
            const int head = v / 6, off = v - head * 6;
            uint4* dv = (uint4*)(gdst + ((size_t)(bh0 + head) * S + s) * HD);
            dv[off] = srcv[v];
        }
        __syncwarp();
    }
}

// ---------------------------------------------------------------------------
// fp16 mma.sync flash attention.
//   P kept in registers (FA2 fragment trick); K/V staging register-pipelined;
//   fragment loads via ldmatrix (3x fewer MIO ops than scalar LDS);
//   O stored fp16.
// ---------------------------------------------------------------------------
#define SKH 56     // K tile row stride (halves); 112 B rows (16B aligned)
#define SVT 72     // Vt row stride (halves); 144 B rows (16B aligned)

__global__ void __launch_bounds__(256) attn_kernel()
{
    __shared__ __align__(16) __half Ks[64 * SKH];   // 7168 B
    __shared__ __align__(16) __half Vt[48 * SVT];   // 6912 B (dim-major)

    const int tid  = threadIdx.x;
    const int wid  = tid >> 5;
    const int lane = tid & 31;
    const int gid  = lane >> 2;
    const int tig  = lane & 3;
    const int hid  = blockIdx.y;
    const int q0   = blockIdx.x * 128;

    // ldmatrix per-lane row addresses (constant across tiles)
    const uint32_t ks_row = smem_u32(Ks) + (uint32_t)((lane & 7) * (SKH * 2) + (lane >> 3) * 16);
    const uint32_t vt_row = smem_u32(Vt) + (uint32_t)((lane & 7) * (SVT * 2) + (lane >> 3) * 16);
    const uint32_t ks_row2 = smem_u32(Ks) + (uint32_t)((lane & 7) * (SKH * 2) + 64 + ((lane >> 3) & 1) * 16);

    // ---- Q fragments straight from gmem (rows >= S read pad: harmless) ----
    uint32_t qa[3][4];
    {
        const __half* Q0 = g_Qh + ((size_t)hid * S + (q0 + wid * 16 + gid)) * HD;
        const __half* Q8 = Q0 + 8 * HD;
        #pragma unroll
        for (int ks = 0; ks < 3; ++ks) {
            qa[ks][0] = *(const uint32_t*)(Q0 + ks * 16 + 2 * tig);
            qa[ks][1] = *(const uint32_t*)(Q8 + ks * 16 + 2 * tig);
            qa[ks][2] = *(const uint32_t*)(Q0 + ks * 16 + 8 + 2 * tig);
            qa[ks][3] = *(const uint32_t*)(Q8 + ks * 16 + 8 + 2 * tig);
        }
    }

    float o[6][4];
    #pragma unroll
    for (int n = 0; n < 6; ++n) { o[n][0] = o[n][1] = o[n][2] = o[n][3] = 0.f; }
    float l0 = 0.f, l1 = 0.f;

    const __half* const Kg = g_Kh + (size_t)hid * S * HD;
    const __half* const Vg = g_Vh + (size_t)hid * S * HD;

    uint32_t kreg[6], vra[3], vrb[3];

    #define LOAD_TILE(j0)                                                          \
    do {                                                                           \
        _Pragma("unroll")                                                          \
        for (int m = 0; m < 6; ++m) {                                              \
            const int u = tid + 256 * m;                                           \
            const int row = u / 24, cu = u - row * 24, gr = (j0) + row;            \
            kreg[m] = (gr < S) ? *(const uint32_t*)(Kg + (size_t)gr * HD + 2 * cu) \
                               : 0u;                                               \
        }                                                                          \
        _Pragma("unroll")                                                          \
        for (int m = 0; m < 3; ++m) {                                              \
            const int u = tid + 256 * m;                                           \
            const int r = u / 24, cc = u - r * 24;                                 \
            const int gr = (j0) + 2 * r;                                           \
            vra[m] = (gr     < S) ? *(const uint32_t*)(Vg + (size_t)gr * HD + 2 * cc) : 0u; \
            vrb[m] = (gr + 1 < S) ? *(const uint32_t*)(Vg + (size_t)(gr + 1) * HD + 2 * cc) : 0u; \
        }                                                                          \
    } while (0)

    #define STORE_TILE()                                                           \
    do {                                                                           \
        _Pragma("unroll")                                                          \
        for (int m = 0; m < 6; ++m) {                                              \
            const int u = tid + 256 * m;                                           \
            const int row = u / 24, cu = u - row * 24;                             \
            *(uint32_t*)&Ks[row * SKH + 2 * cu] = kreg[m];                         \
        }                                                                          \
        _Pragma("unroll")                                                          \
        for (int m = 0; m < 3; ++m) {                                              \
            const int u = tid + 256 * m;                                           \
            const int r = u / 24, cc = u - r * 24;                                 \
            const __half2 ha = *(const __half2*)&vra[m];                           \
            const __half2 hb = *(const __half2*)&vrb[m];                           \
            *(__half2*)&Vt[(2 * cc)     * SVT + 2 * r] =                           \
                __halves2half2(__low2half(ha),  __low2half(hb));                   \
            *(__half2*)&Vt[(2 * cc + 1) * SVT + 2 * r] =                           \
                __halves2half2(__high2half(ha), __high2half(hb));                  \
        }                                                                          \
    } while (0)

    LOAD_TILE(0);

    #pragma unroll 1
    for (int t = 0; t < 10; ++t) {
        const int j0 = t * 64;
        __syncthreads();          // previous tile's compute done; smem free
        STORE_TILE();
        __syncthreads();          // tile t staged
        if (t < 9) LOAD_TILE(j0 + 64);   // issue t+1 LDGs, hide behind MMAs

        // ---- S = Q K^T, exp2, row-sum; pack P as PV A-fragments (registers) ----
        uint32_t ph[8][2];
        #pragma unroll
        for (int nb = 0; nb < 8; ++nb) {
            uint32_t kb4[4], kb2[2];
            ldsm_x4(kb4, ks_row  + (uint32_t)(nb * 8 * SKH * 2));
            ldsm_x2(kb2, ks_row2 + (uint32_t)(nb * 8 * SKH * 2));
            float c[4] = {0.f, 0.f, 0.f, 0.f};
            mma_f16(c, qa[0], kb4[0], kb4[1]);
            mma_f16(c, qa[1], kb4[2], kb4[3]);
            mma_f16(c, qa[2], kb2[0], kb2[1]);
            const int key0 = j0 + nb * 8 + 2 * tig;
            float p0, p1, p2, p3;
            EX2F(p0, c[0]); EX2F(p1, c[1]); EX2F(p2, c[2]); EX2F(p3, c[3]);
            if (key0     >= S) { p0 = 0.f; p2 = 0.f; }
            if (key0 + 1 >= S) { p1 = 0.f; p3 = 0.f; }
            l0 += p0 + p1;
            l1 += p2 + p3;
            const __half2 h01 = __floats2half2_rn(p0, p1);
            const __half2 h23 = __floats2half2_rn(p2, p3);
            ph[nb][0] = *(const uint32_t*)&h01;    // row gid,   cols 2tig..
            ph[nb][1] = *(const uint32_t*)&h23;    // row gid+8, cols 2tig..
        }

        // ---- O += P V  (A from ph; B via ldmatrix on Vt rows = dims) ----
        #pragma unroll
        for (int nb = 0; nb < 6; ++nb) {
            uint32_t vb0[4], vb1[4];
            ldsm_x4(vb0, vt_row + (uint32_t)(nb * 8 * SVT * 2));
            ldsm_x4(vb1, vt_row + (uint32_t)(nb * 8 * SVT * 2 + 64));
            #pragma unroll
            for (int ks = 0; ks < 4; ++ks) {
                uint32_t pa[4];
                pa[0] = ph[2 * ks][0];
                pa[1] = ph[2 * ks][1];
                pa[2] = ph[2 * ks + 1][0];
                pa[3] = ph[2 * ks + 1][1];
                const uint32_t b0 = (ks < 2) ? vb0[2 * ks]     : vb1[2 * (ks - 2)];
                const uint32_t b1 = (ks < 2) ? vb0[2 * ks + 1] : vb1[2 * (ks - 2) + 1];
                mma_f16(o[nb], pa, b0, b1);
            }
        }
    }

    // ---- normalize + store (fp16 O) ----
    l0 += __shfl_xor_sync(0xFFFFFFFFu, l0, 1);
    l0 += __shfl_xor_sync(0xFFFFFFFFu, l0, 2);
    l1 += __shfl_xor_sync(0xFFFFFFFFu, l1, 1);
    l1 += __shfl_xor_sync(0xFFFFFFFFu, l1, 2);
    const float i0 = 1.f / l0;
    const float i1 = 1.f / l1;
    const int r0 = q0 + wid * 16 + gid;
    const int r1 = r0 + 8;
    __half* const Og = g_Oh + (size_t)hid * S * HD;
    #pragma unroll
    for (int nb = 0; nb < 6; ++nb) {
        if (r0 < S) {
            const __half2 h = __floats2half2_rn(o[nb][0] * i0, o[nb][1] * i0);
            *(__half2*)(Og + r0 * HD + nb * 8 + 2 * tig) = h;
        }
        if (r1 < S) {
            const __half2 h = __floats2half2_rn(o[nb][2] * i1, o[nb][3] * i1);
            *(__half2*)(Og + r1 * HD + nb * 8 + 2 * tig) = h;
        }
    }
}

// ---------------------------------------------------------------------------
// Output TLE: warp per token. Gather fp16 O as uint4 (8 halves) runs,
// permute into channel order in smem; contraction pipeline as tle_qkv.
// ---------------------------------------------------------------------------
__global__ void __launch_bounds__(128) tle_o_kernel(
    const float* __restrict__ wo1, const float* __restrict__ wo2,
    const float* __restrict__ wo3, const float* __restrict__ bo,
    float* __restrict__ out)
{
    __shared__ float wS[272];
    __shared__ float T1[4][864];
    __shared__ float T2[4][864];

    const int tid  = threadIdx.x;
    const int w    = tid >> 5;
    const int lane = tid & 31;
    const int tok  = blockIdx.x * 4 + w;
    const int b    = tok / S;
    const int s    = tok - b * S;
    const int bh0  = b * NHEADS;

    for (int idx = tid; idx < 272; idx += 128) {
        wS[idx] = (idx < 64) ? wo1[idx] : (idx < 128) ? wo2[idx - 64] : wo3[idx - 128];
    }

    // gather merge_heads: 96 uint4 (8-half) reads -> channel-order smem
    float* const xsw = T2[w];
    #pragma unroll
    for (int m = 0; m < 3; ++m) {
        const int v = lane + 32 * m;            // 0..95
        const int head = v / 6, off = v - head * 6;
        const uint4 u = ((const uint4*)(g_Oh + ((size_t)(bh0 + head) * S + s) * HD))[off];
        const int h1 = head >> 3, h2 = (head >> 2) & 1, h3 = head & 3;
        const uint32_t uu[4] = {u.x, u.y, u.z, u.w};
        #pragma unroll
        for (int q = 0; q < 4; ++q) {
            const float2 f = __half22float2(*(const __half2*)&uu[q]);
            #pragma unroll
            for (int e = 0; e < 2; ++e) {
                const int dpos = off * 8 + q * 2 + e;
                const int x1 = dpos / 12, rr = dpos - x1 * 12;
                const int y1 = rr / 3,   z1 = rr - y1 * 3;
                const int chan = (2 * x1 + h1) * 96 + (2 * y1 + h2) * 12 + (4 * z1 + h3);
                xsw[chan] = (e == 0) ? f.x : f.y;
            }
        }
    }
    __syncthreads();   // weights ready (block) + xs ready (warp)

    const float* w1 = wS;
    const float* w2 = wS + 64;
    const float* w3 = wS + 128;
    float* const T1w = T1[w];
    float* const T2w = T2[w];

    // x into registers, then same 3-step pipeline
    float xv[24];
    #pragma unroll
    for (int m = 0; m < 3; ++m)
        #pragma unroll
        for (int i = 0; i < 8; ++i)
            xv[i * 3 + m] = xsw[i * 96 + lane + 32 * m];
    __syncwarp();

    #pragma unroll
    for (int a = 0; a < 8; ++a) {
        float wr[8];
        #pragma unroll
        for (int i = 0; i < 8; ++i) wr[i] = w1[a * 8 + i];
        #pragma unroll
        for (int m = 0; m < 3; ++m) {
            float acc = 0.f;
            #pragma unroll
            for (int i = 0; i < 8; ++i) acc += wr[i] * xv[i * 3 + m];
            T1w[a * TST + lane + 32 * m] = acc;
        }
    }
    __syncwarp();

    #pragma unroll
    for (int m = 0; m < 3; ++m) {
        const int r2 = lane + 32 * m;
        const int a2 = r2 / 12, k2 = r2 - a2 * 12;
        float tv[8];
        #pragma unroll
        for (int j = 0; j < 8; ++j) tv[j] = T1w[a2 * TST + j * 12 + k2];
        #pragma unroll
        for (int cc = 0; cc < 8; ++cc) {
            float acc = 0.f;
            #pragma unroll
            for (int j = 0; j < 8; ++j) acc += w2[cc * 8 + j] * tv[j];
            T2w[a2 * TST + cc * 12 + k2] = acc;
        }
    }
    __syncwarp();

    #pragma unroll
    for (int m = 0; m < 2; ++m) {
        const int r3 = lane + 32 * m;
        const int a3 = r3 >> 3, c3 = r3 & 7;
        float uv[12];
        #pragma unroll
        for (int k = 0; k < 12; ++k) uv[k] = T2w[a3 * TST + c3 * 12 + k];
        const float* bb = bo + a3 * 96 + c3 * 12;
        float res[12];
        #pragma unroll
        for (int d = 0; d < 12; ++d) {
            float acc = bb[d];
            #pragma unroll
            for (int k = 0; k < 12; ++k) acc += w3[d * 12 + k] * uv[k];
            res[d] = acc;
        }
        float4* op = (float4*)(out + (size_t)tok * C + a3 * 96 + c3 * 12);
        op[0] = make_float4(res[0], res[1], res[2],  res[3]);
        op[1] = make_float4(res[4], res[5], res[6],  res[7]);
        op[2] = make_float4(res[8], res[9], res[10], res[11]);
    }
}

// ---------------------------------------------------------------------------
// Launch
// ---------------------------------------------------------------------------
extern "C" void kernel_launch(void* const* d_in, const int* in_sizes, int n_in,
                              void* d_out, int out_size)
{
    const float* x   = (const float*)d_in[0];
    const float* wq1 = (const float*)d_in[1];
    const float* wq2 = (const float*)d_in[2];
    const float* wq3 = (const float*)d_in[3];
    const float* bq  = (const float*)d_in[4];
    const float* wk1 = (const float*)d_in[5];
    const float* wk2 = (const float*)d_in[6];
    const float* wk3 = (const float*)d_in[7];
    const float* bk  = (const float*)d_in[8];
    const float* wv1 = (const float*)d_in[9];
    const float* wv2 = (const float*)d_in[10];
    const float* wv3 = (const float*)d_in[11];
    const float* bv  = (const float*)d_in[12];
    const float* wo1 = (const float*)d_in[13];
    const float* wo2 = (const float*)d_in[14];
    const float* wo3 = (const float*)d_in[15];
    const float* bo  = (const float*)d_in[16];
    float* out = (float*)d_out;

    tle_qkv_kernel<<<NTOK / 4, 128>>>(x, wq1, wq2, wq3, bq,
                                         wk1, wk2, wk3, bk,
                                         wv1, wv2, wv3, bv);

    attn_kernel<<<dim3(5, NBH), 256>>>();

    tle_o_kernel<<<NTOK / 4, 128>>>(wo1, wo2, wo3, bo, out);
}